// round 3
// baseline (speedup 1.0000x reference)
#include <cuda_runtime.h>

#define NN   20000
#define EE   320000
#define IND  128
#define HD   64
#define NH   4
#define QKVD 256   // NH * HD
#define NL   3
#define NG   128

// ---------------- scratch (device globals; referenced only in device code) --
__device__ float g_h0[NN * HD];
__device__ float g_h1[NN * HD];
__device__ float g_q[NN * QKVD];
__device__ float g_k[NN * QKVD];
__device__ float g_v[NN * QKVD];
__device__ float g_s[NN * HD];
__device__ float g_alpha[EE * NH];
__device__ int   g_cnt[NN];
__device__ int   g_rowptr[NN + 1];
__device__ int   g_cursor[NN];
__device__ int   g_srcs[EE];
__device__ int   g_use32;   // 1 => edge_index/batch are int32, 0 => int64

// buffer selectors (resolved in device code; avoids cudaGetSymbolAddress)
// 0=g_h0 1=g_h1 2=g_q 3=g_k 4=g_v 5=g_s
__device__ __forceinline__ float* buf_sel(int s) {
    switch (s) {
        case 0: return g_h0;
        case 1: return g_h1;
        case 2: return g_q;
        case 3: return g_k;
        case 4: return g_v;
        default: return g_s;
    }
}

__device__ __forceinline__ int clampN(int i) {
    return i < 0 ? 0 : (i >= NN ? NN - 1 : i);
}
__device__ __forceinline__ int idx_at(const void* p, int i) {
    if (g_use32) return clampN(((const int*)p)[i]);
    return clampN((int)((const long long*)p)[i]);
}

// ---------------- dtype detection (first 32 int64-words = 256 bytes) --------
__global__ void k_detect(const void* __restrict__ ei) {
    const long long* p = (const long long*)ei;
    int t = threadIdx.x;           // 32 threads
    long long v = p[t];
    unsigned bad = __ballot_sync(0xffffffffu, v < 0 || v >= (long long)NN);
    if (t == 0) g_use32 = (bad != 0u) ? 1 : 0;
}

// ---------------- CSR build (counting sort by dst) --------------------------
__global__ void k_zero_cnt() {
    int i = blockIdx.x * blockDim.x + threadIdx.x;
    if (i < NN) g_cnt[i] = 0;
}

__global__ void k_count(const void* __restrict__ ei) {
    int e = blockIdx.x * blockDim.x + threadIdx.x;
    if (e < EE) atomicAdd(&g_cnt[idx_at(ei, EE + e)], 1);
}

__global__ void k_scan() {
    __shared__ int sm[1024];
    __shared__ int s_carry;
    int tid = threadIdx.x;
    if (tid == 0) s_carry = 0;
    __syncthreads();
    for (int base = 0; base < NN; base += 1024) {
        int i = base + tid;
        int val = (i < NN) ? g_cnt[i] : 0;
        sm[tid] = val;
        __syncthreads();
        #pragma unroll
        for (int d = 1; d < 1024; d <<= 1) {
            int tmp = (tid >= d) ? sm[tid - d] : 0;
            __syncthreads();
            sm[tid] += tmp;
            __syncthreads();
        }
        int incl  = sm[tid];
        int carry = s_carry;
        if (i < NN) {
            g_rowptr[i + 1] = carry + incl;
            g_cursor[i]     = carry + incl - val;  // exclusive start
        }
        __syncthreads();
        if (tid == 1023) s_carry = carry + incl;
        __syncthreads();
    }
    if (tid == 0) g_rowptr[0] = 0;
}

__global__ void k_scatter(const void* __restrict__ ei) {
    int e = blockIdx.x * blockDim.x + threadIdx.x;
    if (e < EE) {
        int d   = idx_at(ei, EE + e);
        int pos = atomicAdd(&g_cursor[d], 1);
        g_srcs[pos] = idx_at(ei, e);
    }
}

// ---------------- fp32 tiled GEMM: C[n,M] = A[n,K] @ W[K,M] + bias ----------
// 64x64 tile, 256 threads, each thread 4x4 micro-tile, BK=16. K % 16 == 0.
__global__ void k_gemm(const float* __restrict__ a_ext, int a_sel, int c_sel,
                       const float* __restrict__ W,
                       const float* __restrict__ bias,
                       int n, int K, int M) {
    const float* A = a_ext ? a_ext : buf_sel(a_sel);
    float* C = buf_sel(c_sel);
    __shared__ float As[64][17];
    __shared__ float Bs[16][64];
    int tid  = threadIdx.x;
    int tc   = tid & 15, tr = tid >> 4;
    int row0 = blockIdx.x * 64;
    int col0 = blockIdx.y * 64;
    float acc[4][4] = {};
    int ldr = tid >> 2;
    int ldk = (tid & 3) * 4;
    int bn  = tid & 63;
    for (int k0 = 0; k0 < K; k0 += 16) {
        float4 av = make_float4(0.f, 0.f, 0.f, 0.f);
        int r = row0 + ldr;
        if (r < n) av = *(const float4*)(A + (size_t)r * K + k0 + ldk);
        As[ldr][ldk]     = av.x;
        As[ldr][ldk + 1] = av.y;
        As[ldr][ldk + 2] = av.z;
        As[ldr][ldk + 3] = av.w;
        #pragma unroll
        for (int kk = tid >> 6; kk < 16; kk += 4)
            Bs[kk][bn] = W[(size_t)(k0 + kk) * M + col0 + bn];
        __syncthreads();
        #pragma unroll
        for (int kk = 0; kk < 16; kk++) {
            float4 b = *(const float4*)&Bs[kk][tc * 4];
            #pragma unroll
            for (int i = 0; i < 4; i++) {
                float a = As[tr * 4 + i][kk];
                acc[i][0] += a * b.x;
                acc[i][1] += a * b.y;
                acc[i][2] += a * b.z;
                acc[i][3] += a * b.w;
            }
        }
        __syncthreads();
    }
    #pragma unroll
    for (int i = 0; i < 4; i++) {
        int r = row0 + tr * 4 + i;
        if (r < n) {
            #pragma unroll
            for (int j = 0; j < 4; j++)
                C[(size_t)r * M + col0 + tc * 4 + j] =
                    acc[i][j] + bias[col0 + tc * 4 + j];
        }
    }
}

// ---------------- per-node attention (one warp per node, no atomics) --------
// lane = head*8 + t ; each lane owns 8 contiguous columns of its head.
__global__ void k_attn(int out_sel) {
    int node = (blockIdx.x * blockDim.x + threadIdx.x) >> 5;
    if (node >= NN) return;
    float* hout = buf_sel(out_sel);
    int lane = threadIdx.x & 31;
    int h = lane >> 3, t = lane & 7;
    int col = h * 64 + t * 8;

    const float4* qp = (const float4*)(g_q + (size_t)node * QKVD + col);
    float4 qa = qp[0], qb = qp[1];

    int beg = g_rowptr[node], end = g_rowptr[node + 1];

    // pass 1: logits + running max (exact, per-head in registers)
    float amax = -1e30f;
    for (int p = beg; p < end; ++p) {
        int src = g_srcs[p];
        const float4* kp = (const float4*)(g_k + (size_t)src * QKVD + col);
        float4 ka = kp[0], kb = kp[1];
        float d = qa.x * ka.x + qa.y * ka.y + qa.z * ka.z + qa.w * ka.w
                + qb.x * kb.x + qb.y * kb.y + qb.z * kb.z + qb.w * kb.w;
        d += __shfl_xor_sync(0xffffffffu, d, 1);
        d += __shfl_xor_sync(0xffffffffu, d, 2);
        d += __shfl_xor_sync(0xffffffffu, d, 4);
        d *= 0.125f;               // 1/sqrt(64)
        if (t == 0) g_alpha[p * NH + h] = d;
        amax = fmaxf(amax, d);
    }

    // pass 2: denom + weighted v accumulation (division deferred)
    float denom = 0.f;
    float acc[8] = {0.f, 0.f, 0.f, 0.f, 0.f, 0.f, 0.f, 0.f};
    for (int p = beg; p < end; ++p) {
        int src  = g_srcs[p];
        float ex = expf(g_alpha[p * NH + h] - amax);
        denom += ex;
        const float4* vp = (const float4*)(g_v + (size_t)src * QKVD + col);
        float4 va = vp[0], vb = vp[1];
        acc[0] += ex * va.x; acc[1] += ex * va.y;
        acc[2] += ex * va.z; acc[3] += ex * va.w;
        acc[4] += ex * vb.x; acc[5] += ex * vb.y;
        acc[6] += ex * vb.z; acc[7] += ex * vb.w;
    }
    float inv = denom > 0.f ? 1.f / denom : 0.f;

    // mean over heads: xor 8 / xor 16 sum across the 4 head groups
    #pragma unroll
    for (int j = 0; j < 8; j++) {
        float o = acc[j] * inv;
        o += __shfl_xor_sync(0xffffffffu, o, 8);
        o += __shfl_xor_sync(0xffffffffu, o, 16);
        acc[j] = o;
    }

    if (h == 0) {
        const float* sp = g_s + (size_t)node * HD + t * 8;
        float* op = hout + (size_t)node * HD + t * 8;
        #pragma unroll
        for (int j = 0; j < 8; j++) {
            float val = 0.25f * acc[j] + sp[j];   // head mean + skip (bias in s)
            op[j] = fmaxf(val, 0.f);              // layer ReLU
        }
    }
}

// ---------------- global add pool -------------------------------------------
__global__ void k_pool_zero(float* out) {
    int i = blockIdx.x * blockDim.x + threadIdx.x;
    if (i < NG * HD) out[i] = 0.f;
}

__global__ void k_pool(int in_sel, const void* __restrict__ batch,
                       float* out) {
    const float* hh = buf_sel(in_sel);
    int i = blockIdx.x * blockDim.x + threadIdx.x;
    if (i < NN * HD) {
        int row = i >> 6;
        int g = g_use32 ? ((const int*)batch)[row]
                        : (int)((const long long*)batch)[row];
        g = g < 0 ? 0 : (g >= NG ? NG - 1 : g);
        atomicAdd(&out[g * HD + (i & 63)], hh[i]);
    }
}

// ---------------- host ------------------------------------------------------
extern "C" void kernel_launch(void* const* d_in, const int* in_sizes, int n_in,
                              void* d_out, int out_size) {
    (void)in_sizes; (void)n_in; (void)out_size;
    const float* x     = (const float*)d_in[0];
    const void*  ei    = d_in[1];
    const void*  batch = d_in[2];
    const float* lin_W = (const float*)d_in[3];
    const float* lin_b = (const float*)d_in[4];
    const float* Wq = (const float*)d_in[5];
    const float* bq = (const float*)d_in[6];
    const float* Wk = (const float*)d_in[7];
    const float* bk = (const float*)d_in[8];
    const float* Wv = (const float*)d_in[9];
    const float* bv = (const float*)d_in[10];
    const float* Ws = (const float*)d_in[11];
    const float* bs = (const float*)d_in[12];

    // dtype detect + CSR by dst
    k_detect<<<1, 32>>>(ei);
    k_zero_cnt<<<(NN + 255) / 256, 256>>>();
    k_count<<<(EE + 255) / 256, 256>>>(ei);
    k_scan<<<1, 1024>>>();
    k_scatter<<<(EE + 255) / 256, 256>>>(ei);

    const int RT = (NN + 63) / 64;  // row tiles

    // input projection: h0 = x @ lin_W + lin_b
    k_gemm<<<dim3(RT, 1), 256>>>(x, 0, 0, lin_W, lin_b, NN, IND, HD);

    int hin = 0, hou = 1;
    for (int l = 0; l < NL; l++) {
        const float* wq = Wq + (size_t)l * HD * QKVD;
        const float* wk = Wk + (size_t)l * HD * QKVD;
        const float* wv = Wv + (size_t)l * HD * QKVD;
        const float* ws = Ws + (size_t)l * HD * HD;
        k_gemm<<<dim3(RT, QKVD / 64), 256>>>(nullptr, hin, 2, wq, bq + (size_t)l * QKVD, NN, HD, QKVD);
        k_gemm<<<dim3(RT, QKVD / 64), 256>>>(nullptr, hin, 3, wk, bk + (size_t)l * QKVD, NN, HD, QKVD);
        k_gemm<<<dim3(RT, QKVD / 64), 256>>>(nullptr, hin, 4, wv, bv + (size_t)l * QKVD, NN, HD, QKVD);
        k_gemm<<<dim3(RT, 1), 256>>>(nullptr, hin, 5, ws, bs + (size_t)l * HD, NN, HD, HD);
        k_attn<<<(NN * 32 + 255) / 256, 256>>>(hou);
        int tmp = hin; hin = hou; hou = tmp;
    }

    k_pool_zero<<<(NG * HD + 255) / 256, 256>>>((float*)d_out);
    k_pool<<<(NN * HD + 255) / 256, 256>>>(hin, batch, (float*)d_out);
}

// round 4
// speedup vs baseline: 1.3117x; 1.3117x over previous
#include <cuda_runtime.h>

#define NN   20000
#define EE   320000
#define IND  128
#define HD   64
#define NH   4
#define QKVD 256   // NH * HD
#define NL   3
#define NG   128

// ---------------- scratch (device globals; referenced only in device code) --
__device__ float g_h0[NN * HD];
__device__ float g_h1[NN * HD];
__device__ float g_q[NN * QKVD];
__device__ float g_k[NN * QKVD];
__device__ float g_v[NN * QKVD];
__device__ float g_s[NN * HD];
__device__ int   g_cnt[NN];
__device__ int   g_rowptr[NN + 1];
__device__ int   g_cursor[NN];
__device__ int   g_srcs[EE];
__device__ int   g_use32;   // 1 => edge_index/batch are int32, 0 => int64

// buffer selectors (resolved in device code)
// 0=g_h0 1=g_h1 2=g_q 3=g_k 4=g_v 5=g_s
__device__ __forceinline__ float* buf_sel(int s) {
    switch (s) {
        case 0: return g_h0;
        case 1: return g_h1;
        case 2: return g_q;
        case 3: return g_k;
        case 4: return g_v;
        default: return g_s;
    }
}

__device__ __forceinline__ int clampN(int i) {
    return i < 0 ? 0 : (i >= NN ? NN - 1 : i);
}
__device__ __forceinline__ int idx_at(const void* p, int i) {
    if (g_use32) return clampN(((const int*)p)[i]);
    return clampN((int)((const long long*)p)[i]);
}

// ---------------- dtype detection -------------------------------------------
__global__ void k_detect(const void* __restrict__ ei) {
    const long long* p = (const long long*)ei;
    int t = threadIdx.x;           // 32 threads
    long long v = p[t];
    unsigned bad = __ballot_sync(0xffffffffu, v < 0 || v >= (long long)NN);
    if (t == 0) g_use32 = (bad != 0u) ? 1 : 0;
}

// ---------------- CSR build (counting sort by dst) --------------------------
__global__ void k_zero_cnt() {
    int i = blockIdx.x * blockDim.x + threadIdx.x;
    if (i < NN) g_cnt[i] = 0;
}

__global__ void k_count(const void* __restrict__ ei) {
    int e = blockIdx.x * blockDim.x + threadIdx.x;
    if (e < EE) atomicAdd(&g_cnt[idx_at(ei, EE + e)], 1);
}

// 1024 threads, each scans a 20-element chunk serially; shuffle-scan partials.
#define SCAN_CH 20
__global__ void k_scan() {
    __shared__ int warp_incl[32];
    int t    = threadIdx.x;
    int lane = t & 31, wid = t >> 5;
    int base = t * SCAN_CH;

    int sum = 0;
    #pragma unroll
    for (int i = 0; i < SCAN_CH; i++) {
        int idx = base + i;
        if (idx < NN) sum += g_cnt[idx];
    }
    // warp inclusive scan
    int incl = sum;
    #pragma unroll
    for (int d = 1; d < 32; d <<= 1) {
        int nb = __shfl_up_sync(0xffffffffu, incl, d);
        if (lane >= d) incl += nb;
    }
    if (lane == 31) warp_incl[wid] = incl;
    __syncthreads();
    if (wid == 0) {
        int ws = warp_incl[lane];
        #pragma unroll
        for (int d = 1; d < 32; d <<= 1) {
            int nb = __shfl_up_sync(0xffffffffu, ws, d);
            if (lane >= d) ws += nb;
        }
        warp_incl[lane] = ws;
    }
    __syncthreads();
    int warp_off = (wid == 0) ? 0 : warp_incl[wid - 1];
    int run = warp_off + (incl - sum);   // exclusive base for this thread
    #pragma unroll
    for (int i = 0; i < SCAN_CH; i++) {
        int idx = base + i;
        if (idx < NN) {
            int v = g_cnt[idx];          // L1 hit (read in phase 1)
            g_cursor[idx] = run;
            run += v;
            g_rowptr[idx + 1] = run;
        }
    }
    if (t == 0) g_rowptr[0] = 0;
}

__global__ void k_scatter(const void* __restrict__ ei) {
    int e = blockIdx.x * blockDim.x + threadIdx.x;
    if (e < EE) {
        int d   = idx_at(ei, EE + e);
        int pos = atomicAdd(&g_cursor[d], 1);
        g_srcs[pos] = idx_at(ei, e);
    }
}

// ---------------- fp32 GEMM core: 64x64 tile, BK=64, 256 thr, 4x4 micro ----
__device__ __forceinline__ void gemm_tile(
    const float* __restrict__ A, const float* __restrict__ W,
    const float* __restrict__ bias, float* __restrict__ C,
    int n, int K, int Mw, int Mc, int row0, int colW, int colC,
    float (&As)[64][68], float (&Bs)[64][68]) {

    int tid = threadIdx.x;
    int tc  = tid & 15, tr = tid >> 4;
    float acc[4][4] = {};

    int lr = tid >> 2;            // 0..63
    int lc = (tid & 3) * 16;      // 0,16,32,48

    for (int k0 = 0; k0 < K; k0 += 64) {
        // load A tile [64 rows x 64 k]
        {
            int r = row0 + lr;
            #pragma unroll
            for (int i = 0; i < 4; i++) {
                float4 av = make_float4(0.f, 0.f, 0.f, 0.f);
                if (r < n) av = *(const float4*)(A + (size_t)r * K + k0 + lc + i * 4);
                *(float4*)&As[lr][lc + i * 4] = av;
            }
        }
        // load B tile [64 k x 64 cols]
        {
            #pragma unroll
            for (int i = 0; i < 4; i++) {
                float4 bv = *(const float4*)(W + (size_t)(k0 + lr) * Mw + colW + lc + i * 4);
                *(float4*)&Bs[lr][lc + i * 4] = bv;
            }
        }
        __syncthreads();
        #pragma unroll
        for (int kk = 0; kk < 64; kk++) {
            float4 b = *(const float4*)&Bs[kk][tc * 4];
            #pragma unroll
            for (int i = 0; i < 4; i++) {
                float a = As[tr * 4 + i][kk];
                acc[i][0] += a * b.x;
                acc[i][1] += a * b.y;
                acc[i][2] += a * b.z;
                acc[i][3] += a * b.w;
            }
        }
        __syncthreads();
    }
    #pragma unroll
    for (int i = 0; i < 4; i++) {
        int r = row0 + tr * 4 + i;
        if (r < n) {
            float4 o;
            o.x = acc[i][0] + bias[colW + tc * 4];
            o.y = acc[i][1] + bias[colW + tc * 4 + 1];
            o.z = acc[i][2] + bias[colW + tc * 4 + 2];
            o.w = acc[i][3] + bias[colW + tc * 4 + 3];
            *(float4*)(C + (size_t)r * Mc + colC + tc * 4) = o;
        }
    }
}

// generic GEMM (used for input projection)
__global__ void k_gemm(const float* __restrict__ a_ext, int a_sel, int c_sel,
                       const float* __restrict__ W,
                       const float* __restrict__ bias,
                       int n, int K, int M) {
    __shared__ float As[64][68];
    __shared__ float Bs[64][68];
    const float* A = a_ext ? a_ext : buf_sel(a_sel);
    float* C = buf_sel(c_sel);
    gemm_tile(A, W, bias, C, n, K, M, M,
              blockIdx.x * 64, blockIdx.y * 64, blockIdx.y * 64, As, Bs);
}

// fused q/k/v/s projections for one layer: grid.y = 13 column tiles
// tiles 0-3 -> q, 4-7 -> k, 8-11 -> v, 12 -> s
__global__ void k_gemm_qkvs(int a_sel,
                            const float* __restrict__ Wq, const float* __restrict__ bq,
                            const float* __restrict__ Wk, const float* __restrict__ bk,
                            const float* __restrict__ Wv, const float* __restrict__ bv,
                            const float* __restrict__ Ws, const float* __restrict__ bs) {
    __shared__ float As[64][68];
    __shared__ float Bs[64][68];
    const float* A = buf_sel(a_sel);
    int ct = blockIdx.y;
    const float* W; const float* bias; float* C; int M; int col;
    if (ct < 4)       { W = Wq; bias = bq; C = g_q; M = QKVD; col = ct * 64; }
    else if (ct < 8)  { W = Wk; bias = bk; C = g_k; M = QKVD; col = (ct - 4) * 64; }
    else if (ct < 12) { W = Wv; bias = bv; C = g_v; M = QKVD; col = (ct - 8) * 64; }
    else              { W = Ws; bias = bs; C = g_s; M = HD;   col = 0; }
    gemm_tile(A, W, bias, C, NN, HD, M, M, blockIdx.x * 64, col, col, As, Bs);
}

// ---------------- per-node attention: single-pass online softmax ------------
// one warp per node; lane = head*8 + t; each lane owns 8 contiguous columns.
__global__ void k_attn(int out_sel) {
    int node = (blockIdx.x * blockDim.x + threadIdx.x) >> 5;
    if (node >= NN) return;
    float* hout = buf_sel(out_sel);
    int lane = threadIdx.x & 31;
    int h = lane >> 3, t = lane & 7;
    int col = h * 64 + t * 8;

    const float4* qp = (const float4*)(g_q + (size_t)node * QKVD + col);
    float4 qa = qp[0], qb = qp[1];

    int beg = g_rowptr[node], end = g_rowptr[node + 1];

    float m = -1e30f, denom = 0.f;
    float acc[8] = {0.f, 0.f, 0.f, 0.f, 0.f, 0.f, 0.f, 0.f};

    for (int p = beg; p < end; ++p) {
        int src = g_srcs[p];
        const float4* kp = (const float4*)(g_k + (size_t)src * QKVD + col);
        const float4* vp = (const float4*)(g_v + (size_t)src * QKVD + col);
        float4 ka = kp[0], kb = kp[1];
        float4 va = vp[0], vb = vp[1];

        float d = qa.x * ka.x + qa.y * ka.y + qa.z * ka.z + qa.w * ka.w
                + qb.x * kb.x + qb.y * kb.y + qb.z * kb.z + qb.w * kb.w;
        d += __shfl_xor_sync(0xffffffffu, d, 1);
        d += __shfl_xor_sync(0xffffffffu, d, 2);
        d += __shfl_xor_sync(0xffffffffu, d, 4);
        d *= 0.125f;                       // 1/sqrt(64)

        float nm   = fmaxf(m, d);
        float corr = __expf(m - nm);       // first iter: exp(-huge) -> 0
        float ex   = __expf(d - nm);
        m = nm;
        denom = denom * corr + ex;
        acc[0] = acc[0] * corr + ex * va.x;
        acc[1] = acc[1] * corr + ex * va.y;
        acc[2] = acc[2] * corr + ex * va.z;
        acc[3] = acc[3] * corr + ex * va.w;
        acc[4] = acc[4] * corr + ex * vb.x;
        acc[5] = acc[5] * corr + ex * vb.y;
        acc[6] = acc[6] * corr + ex * vb.z;
        acc[7] = acc[7] * corr + ex * vb.w;
    }
    float inv = denom > 0.f ? 1.f / denom : 0.f;

    // mean over heads: xor 8 / xor 16 sums across the 4 head groups
    #pragma unroll
    for (int j = 0; j < 8; j++) {
        float o = acc[j] * inv;
        o += __shfl_xor_sync(0xffffffffu, o, 8);
        o += __shfl_xor_sync(0xffffffffu, o, 16);
        acc[j] = o;
    }

    if (h == 0) {
        const float* sp = g_s + (size_t)node * HD + t * 8;
        float* op = hout + (size_t)node * HD + t * 8;
        #pragma unroll
        for (int j = 0; j < 8; j++) {
            float val = 0.25f * acc[j] + sp[j];   // head mean + skip
            op[j] = fmaxf(val, 0.f);              // layer ReLU
        }
    }
}

// ---------------- global add pool -------------------------------------------
__global__ void k_pool_zero(float* out) {
    int i = blockIdx.x * blockDim.x + threadIdx.x;
    if (i < NG * HD) out[i] = 0.f;
}

__global__ void k_pool(int in_sel, const void* __restrict__ batch,
                       float* out) {
    const float* hh = buf_sel(in_sel);
    int i = blockIdx.x * blockDim.x + threadIdx.x;
    if (i < NN * HD) {
        int row = i >> 6;
        int g = g_use32 ? ((const int*)batch)[row]
                        : (int)((const long long*)batch)[row];
        g = g < 0 ? 0 : (g >= NG ? NG - 1 : g);
        atomicAdd(&out[g * HD + (i & 63)], hh[i]);
    }
}

// ---------------- host ------------------------------------------------------
extern "C" void kernel_launch(void* const* d_in, const int* in_sizes, int n_in,
                              void* d_out, int out_size) {
    (void)in_sizes; (void)n_in; (void)out_size;
    const float* x     = (const float*)d_in[0];
    const void*  ei    = d_in[1];
    const void*  batch = d_in[2];
    const float* lin_W = (const float*)d_in[3];
    const float* lin_b = (const float*)d_in[4];
    const float* Wq = (const float*)d_in[5];
    const float* bq = (const float*)d_in[6];
    const float* Wk = (const float*)d_in[7];
    const float* bk = (const float*)d_in[8];
    const float* Wv = (const float*)d_in[9];
    const float* bv = (const float*)d_in[10];
    const float* Ws = (const float*)d_in[11];
    const float* bs = (const float*)d_in[12];

    // dtype detect + CSR by dst
    k_detect<<<1, 32>>>(ei);
    k_zero_cnt<<<(NN + 255) / 256, 256>>>();
    k_count<<<(EE + 255) / 256, 256>>>(ei);
    k_scan<<<1, 1024>>>();
    k_scatter<<<(EE + 255) / 256, 256>>>(ei);

    const int RT = (NN + 63) / 64;  // row tiles

    // input projection: h0 = x @ lin_W + lin_b
    k_gemm<<<dim3(RT, 1), 256>>>(x, 0, 0, lin_W, lin_b, NN, IND, HD);

    int hin = 0, hou = 1;
    for (int l = 0; l < NL; l++) {
        k_gemm_qkvs<<<dim3(RT, 13), 256>>>(hin,
            Wq + (size_t)l * HD * QKVD, bq + (size_t)l * QKVD,
            Wk + (size_t)l * HD * QKVD, bk + (size_t)l * QKVD,
            Wv + (size_t)l * HD * QKVD, bv + (size_t)l * QKVD,
            Ws + (size_t)l * HD * HD,   bs + (size_t)l * HD);
        k_attn<<<(NN * 32 + 255) / 256, 256>>>(hou);
        int tmp = hin; hin = hou; hou = tmp;
    }

    k_pool_zero<<<(NG * HD + 255) / 256, 256>>>((float*)d_out);
    k_pool<<<(NN * HD + 255) / 256, 256>>>(hin, batch, (float*)d_out);
}

// round 5
// speedup vs baseline: 1.7698x; 1.3493x over previous
#include <cuda_runtime.h>
#include <cstdint>

#define NN   20000
#define EE   320000
#define IND  128
#define HD   64
#define NH   4
#define QKVD 256   // NH * HD
#define NL   3
#define NG   128
#define NB   79    // scan blocks: ceil(NN/256)

// ---------------- scratch (device globals) ----------------------------------
__device__ float g_h0[NN * HD];
__device__ float g_h1[NN * HD];
__device__ float g_q[NN * QKVD];
__device__ float g_k[NN * QKVD];
__device__ float g_v[NN * QKVD];
__device__ float g_s[NN * HD];
__device__ int   g_cnt[NN];
__device__ int   g_rowptr[NN + 1];
__device__ int   g_cursor[NN];
__device__ int   g_srcs[EE];
__device__ int   g_bsum[128];
__device__ int   g_boff[128];
__device__ int   g_use32;   // 1 => edge_index/batch are int32, 0 => int64

// 0=g_h0 1=g_h1 (others unused by sel now)
__device__ __forceinline__ float* buf_sel(int s) {
    return s == 0 ? g_h0 : g_h1;
}

__device__ __forceinline__ int clampN(int i) {
    return i < 0 ? 0 : (i >= NN ? NN - 1 : i);
}
__device__ __forceinline__ int idx_at(const void* p, int i) {
    if (g_use32) return clampN(((const int*)p)[i]);
    return clampN((int)((const long long*)p)[i]);
}

// ---------------- dtype detection -------------------------------------------
__global__ void k_detect(const void* __restrict__ ei) {
    const long long* p = (const long long*)ei;
    int t = threadIdx.x;           // 32 threads
    long long v = p[t];
    unsigned bad = __ballot_sync(0xffffffffu, v < 0 || v >= (long long)NN);
    if (t == 0) g_use32 = (bad != 0u) ? 1 : 0;
}

// ---------------- CSR build (counting sort by dst) --------------------------
__global__ void k_zero_cnt() {
    int i = blockIdx.x * blockDim.x + threadIdx.x;
    if (i < NN) g_cnt[i] = 0;
}

__global__ void k_count(const void* __restrict__ ei) {
    int e = blockIdx.x * blockDim.x + threadIdx.x;
    if (e < EE) atomicAdd(&g_cnt[idx_at(ei, EE + e)], 1);
}

// phase 1: per-block sums (NB blocks x 256)
__global__ void k_scan1() {
    __shared__ int ws[8];
    int t = threadIdx.x, lane = t & 31, wid = t >> 5;
    int i = blockIdx.x * 256 + t;
    int v = (i < NN) ? g_cnt[i] : 0;
    int s = v;
    #pragma unroll
    for (int d = 16; d > 0; d >>= 1) s += __shfl_xor_sync(0xffffffffu, s, d);
    if (lane == 0) ws[wid] = s;
    __syncthreads();
    if (t < 8) {
        int x = ws[t];
        #pragma unroll
        for (int d = 4; d > 0; d >>= 1) x += __shfl_xor_sync(0xffu, x, d);
        if (t == 0) g_bsum[blockIdx.x] = x;
    }
}

// phase 2: exclusive scan of NB block sums (1 block, 128 threads)
__global__ void k_scan2() {
    __shared__ int wsum[4];
    int t = threadIdx.x, lane = t & 31, wid = t >> 5;
    int v = (t < NB) ? g_bsum[t] : 0;
    int incl = v;
    #pragma unroll
    for (int d = 1; d < 32; d <<= 1) {
        int nb = __shfl_up_sync(0xffffffffu, incl, d);
        if (lane >= d) incl += nb;
    }
    if (lane == 31) wsum[wid] = incl;
    __syncthreads();
    int off = 0;
    for (int w = 0; w < wid; w++) off += wsum[w];
    if (t < NB) g_boff[t] = off + incl - v;   // exclusive
}

// phase 3: per-block scan + write rowptr/cursor
__global__ void k_scan3() {
    __shared__ int wincl[8];
    int t = threadIdx.x, lane = t & 31, wid = t >> 5;
    int i = blockIdx.x * 256 + t;
    int v = (i < NN) ? g_cnt[i] : 0;
    int incl = v;
    #pragma unroll
    for (int d = 1; d < 32; d <<= 1) {
        int nb = __shfl_up_sync(0xffffffffu, incl, d);
        if (lane >= d) incl += nb;
    }
    if (lane == 31) wincl[wid] = incl;
    __syncthreads();
    int woff = 0;
    for (int w = 0; w < wid; w++) woff += wincl[w];
    int excl = g_boff[blockIdx.x] + woff + incl - v;
    if (i < NN) {
        g_cursor[i] = excl;
        g_rowptr[i + 1] = excl + v;
        if (i == 0) g_rowptr[0] = 0;
    }
}

__global__ void k_scatter(const void* __restrict__ ei) {
    int e = blockIdx.x * blockDim.x + threadIdx.x;
    if (e < EE) {
        int d   = idx_at(ei, EE + e);
        int pos = atomicAdd(&g_cursor[d], 1);
        g_srcs[pos] = idx_at(ei, e);
    }
}

// ---------------- TF32 tensor-core GEMM -------------------------------------
__device__ __forceinline__ uint32_t f2tf32(float f) {
    uint32_t u;
    asm("cvt.rna.tf32.f32 %0, %1;" : "=r"(u) : "f"(f));
    return u;
}

__device__ __forceinline__ void mma_tf32(float& c0, float& c1, float& c2, float& c3,
                                         uint32_t a0, uint32_t a1, uint32_t a2, uint32_t a3,
                                         uint32_t b0, uint32_t b1) {
    asm volatile(
        "mma.sync.aligned.m16n8k8.row.col.f32.tf32.tf32.f32 "
        "{%0,%1,%2,%3},{%4,%5,%6,%7},{%8,%9},{%0,%1,%2,%3};"
        : "+f"(c0), "+f"(c1), "+f"(c2), "+f"(c3)
        : "r"(a0), "r"(a1), "r"(a2), "r"(a3), "r"(b0), "r"(b1));
}

// core: C[64 rows x 64 cols] tile via 8 warps (4m x 2n), warp tile m16n32.
// A row-major [n,K]; W row-major [K,Mw]; bias over W cols.
__device__ __forceinline__ void gemm_tile_tf32(
    const float* __restrict__ A, const float* __restrict__ W,
    const float* __restrict__ bias, float* __restrict__ C,
    int n, int K, int Mw, int Mc, int row0, int colW, int colC) {

    __shared__ float As[64][68];
    __shared__ float Bs[64][68];

    int tid  = threadIdx.x;
    int lane = tid & 31;
    int wid  = tid >> 5;
    int wm   = wid & 3;          // m quadrant: rows wm*16..+15
    int wn   = wid >> 2;         // n half: cols wn*32..+31
    int g    = lane >> 2;        // groupID 0..7
    int tg   = lane & 3;         // thread-in-group 0..3

    float acc[4][4] = {};        // 4 n-frags x 4 regs

    for (int kt = 0; kt < K; kt += 64) {
        // load A tile: 1024 float4, 4 per thread
        #pragma unroll
        for (int i = 0; i < 4; i++) {
            int idx = i * 256 + tid;
            int r = idx >> 4, c4 = idx & 15;
            float4 av = make_float4(0.f, 0.f, 0.f, 0.f);
            int gr = row0 + r;
            if (gr < n) av = *(const float4*)(A + (size_t)gr * K + kt + c4 * 4);
            *(float4*)&As[r][c4 * 4] = av;
        }
        // load B tile
        #pragma unroll
        for (int i = 0; i < 4; i++) {
            int idx = i * 256 + tid;
            int r = idx >> 4, c4 = idx & 15;
            float4 bv = *(const float4*)(W + (size_t)(kt + r) * Mw + colW + c4 * 4);
            *(float4*)&Bs[r][c4 * 4] = bv;
        }
        __syncthreads();

        #pragma unroll
        for (int ks = 0; ks < 8; ks++) {
            int k0 = ks * 8;
            uint32_t a0 = f2tf32(As[wm * 16 + g][k0 + tg]);
            uint32_t a1 = f2tf32(As[wm * 16 + g + 8][k0 + tg]);
            uint32_t a2 = f2tf32(As[wm * 16 + g][k0 + tg + 4]);
            uint32_t a3 = f2tf32(As[wm * 16 + g + 8][k0 + tg + 4]);
            #pragma unroll
            for (int j = 0; j < 4; j++) {
                int n0 = wn * 32 + j * 8;
                uint32_t b0 = f2tf32(Bs[k0 + tg][n0 + g]);
                uint32_t b1 = f2tf32(Bs[k0 + tg + 4][n0 + g]);
                mma_tf32(acc[j][0], acc[j][1], acc[j][2], acc[j][3],
                         a0, a1, a2, a3, b0, b1);
            }
        }
        __syncthreads();
    }

    // epilogue: c0/c1 -> row g, cols 2tg,2tg+1 ; c2/c3 -> row g+8
    #pragma unroll
    for (int j = 0; j < 4; j++) {
        int n0 = wn * 32 + j * 8;
        int cw = colW + n0 + tg * 2;
        int cc = colC + n0 + tg * 2;
        float b0 = bias[cw], b1 = bias[cw + 1];
        int r0 = row0 + wm * 16 + g;
        int r1 = r0 + 8;
        if (r0 < n) {
            float2 o = make_float2(acc[j][0] + b0, acc[j][1] + b1);
            *(float2*)(C + (size_t)r0 * Mc + cc) = o;
        }
        if (r1 < n) {
            float2 o = make_float2(acc[j][2] + b0, acc[j][3] + b1);
            *(float2*)(C + (size_t)r1 * Mc + cc) = o;
        }
    }
}

// input projection: h0 = x @ lin_W + lin_b   (K=IND, M=HD)
__global__ __launch_bounds__(256) void k_gemm_in(const float* __restrict__ x,
                                                 const float* __restrict__ W,
                                                 const float* __restrict__ bias) {
    gemm_tile_tf32(x, W, bias, g_h0, NN, IND, HD, HD, blockIdx.x * 64, 0, 0);
}

// fused q/k/v/s projections: grid.y = 13 col tiles (0-3 q, 4-7 k, 8-11 v, 12 s)
__global__ __launch_bounds__(256) void k_gemm_qkvs(int a_sel,
        const float* __restrict__ Wq, const float* __restrict__ bq,
        const float* __restrict__ Wk, const float* __restrict__ bk,
        const float* __restrict__ Wv, const float* __restrict__ bv,
        const float* __restrict__ Ws, const float* __restrict__ bs) {
    const float* A = buf_sel(a_sel);
    int ct = blockIdx.y;
    const float* W; const float* bias; float* C; int M; int col;
    if (ct < 4)       { W = Wq; bias = bq; C = g_q; M = QKVD; col = ct * 64; }
    else if (ct < 8)  { W = Wk; bias = bk; C = g_k; M = QKVD; col = (ct - 4) * 64; }
    else if (ct < 12) { W = Wv; bias = bv; C = g_v; M = QKVD; col = (ct - 8) * 64; }
    else              { W = Ws; bias = bs; C = g_s; M = HD;   col = 0; }
    gemm_tile_tf32(A, W, bias, C, NN, HD, M, M, blockIdx.x * 64, col, col);
}

// ---------------- per-node attention: single-pass online softmax ------------
__global__ void k_attn(int out_sel) {
    int node = (blockIdx.x * blockDim.x + threadIdx.x) >> 5;
    if (node >= NN) return;
    float* hout = buf_sel(out_sel);
    int lane = threadIdx.x & 31;
    int h = lane >> 3, t = lane & 7;
    int col = h * 64 + t * 8;

    const float4* qp = (const float4*)(g_q + (size_t)node * QKVD + col);
    float4 qa = qp[0], qb = qp[1];

    int beg = g_rowptr[node], end = g_rowptr[node + 1];

    float m = -1e30f, denom = 0.f;
    float acc[8] = {0.f, 0.f, 0.f, 0.f, 0.f, 0.f, 0.f, 0.f};

    for (int p = beg; p < end; ++p) {
        int src = g_srcs[p];
        const float4* kp = (const float4*)(g_k + (size_t)src * QKVD + col);
        const float4* vp = (const float4*)(g_v + (size_t)src * QKVD + col);
        float4 ka = kp[0], kb = kp[1];
        float4 va = vp[0], vb = vp[1];

        float d = qa.x * ka.x + qa.y * ka.y + qa.z * ka.z + qa.w * ka.w
                + qb.x * kb.x + qb.y * kb.y + qb.z * kb.z + qb.w * kb.w;
        d += __shfl_xor_sync(0xffffffffu, d, 1);
        d += __shfl_xor_sync(0xffffffffu, d, 2);
        d += __shfl_xor_sync(0xffffffffu, d, 4);
        d *= 0.125f;                       // 1/sqrt(64)

        float nm   = fmaxf(m, d);
        float corr = __expf(m - nm);
        float ex   = __expf(d - nm);
        m = nm;
        denom = denom * corr + ex;
        acc[0] = acc[0] * corr + ex * va.x;
        acc[1] = acc[1] * corr + ex * va.y;
        acc[2] = acc[2] * corr + ex * va.z;
        acc[3] = acc[3] * corr + ex * va.w;
        acc[4] = acc[4] * corr + ex * vb.x;
        acc[5] = acc[5] * corr + ex * vb.y;
        acc[6] = acc[6] * corr + ex * vb.z;
        acc[7] = acc[7] * corr + ex * vb.w;
    }
    float inv = denom > 0.f ? 1.f / denom : 0.f;

    #pragma unroll
    for (int j = 0; j < 8; j++) {
        float o = acc[j] * inv;
        o += __shfl_xor_sync(0xffffffffu, o, 8);
        o += __shfl_xor_sync(0xffffffffu, o, 16);
        acc[j] = o;
    }

    if (h == 0) {
        const float* sp = g_s + (size_t)node * HD + t * 8;
        float* op = hout + (size_t)node * HD + t * 8;
        #pragma unroll
        for (int j = 0; j < 8; j++) {
            float val = 0.25f * acc[j] + sp[j];   // head mean + skip
            op[j] = fmaxf(val, 0.f);              // ReLU
        }
    }
}

// ---------------- global add pool -------------------------------------------
__global__ void k_pool_zero(float* out) {
    int i = blockIdx.x * blockDim.x + threadIdx.x;
    if (i < NG * HD) out[i] = 0.f;
}

__global__ void k_pool(int in_sel, const void* __restrict__ batch,
                       float* out) {
    const float* hh = buf_sel(in_sel);
    int i = blockIdx.x * blockDim.x + threadIdx.x;
    if (i < NN * HD) {
        int row = i >> 6;
        int g = g_use32 ? ((const int*)batch)[row]
                        : (int)((const long long*)batch)[row];
        g = g < 0 ? 0 : (g >= NG ? NG - 1 : g);
        atomicAdd(&out[g * HD + (i & 63)], hh[i]);
    }
}

// ---------------- host ------------------------------------------------------
extern "C" void kernel_launch(void* const* d_in, const int* in_sizes, int n_in,
                              void* d_out, int out_size) {
    (void)in_sizes; (void)n_in; (void)out_size;
    const float* x     = (const float*)d_in[0];
    const void*  ei    = d_in[1];
    const void*  batch = d_in[2];
    const float* lin_W = (const float*)d_in[3];
    const float* lin_b = (const float*)d_in[4];
    const float* Wq = (const float*)d_in[5];
    const float* bq = (const float*)d_in[6];
    const float* Wk = (const float*)d_in[7];
    const float* bk = (const float*)d_in[8];
    const float* Wv = (const float*)d_in[9];
    const float* bv = (const float*)d_in[10];
    const float* Ws = (const float*)d_in[11];
    const float* bs = (const float*)d_in[12];

    // dtype detect + CSR by dst
    k_detect<<<1, 32>>>(ei);
    k_zero_cnt<<<(NN + 255) / 256, 256>>>();
    k_count<<<(EE + 255) / 256, 256>>>(ei);
    k_scan1<<<NB, 256>>>();
    k_scan2<<<1, 128>>>();
    k_scan3<<<NB, 256>>>();
    k_scatter<<<(EE + 255) / 256, 256>>>(ei);

    const int RT = (NN + 63) / 64;  // 313 row tiles

    k_gemm_in<<<dim3(RT, 1), 256>>>(x, lin_W, lin_b);

    int hin = 0, hou = 1;
    for (int l = 0; l < NL; l++) {
        k_gemm_qkvs<<<dim3(RT, 13), 256>>>(hin,
            Wq + (size_t)l * HD * QKVD, bq + (size_t)l * QKVD,
            Wk + (size_t)l * HD * QKVD, bk + (size_t)l * QKVD,
            Wv + (size_t)l * HD * QKVD, bv + (size_t)l * QKVD,
            Ws + (size_t)l * HD * HD,   bs + (size_t)l * HD);
        k_attn<<<(NN * 32 + 255) / 256, 256>>>(hou);
        int tmp = hin; hin = hou; hou = tmp;
    }

    k_pool_zero<<<(NG * HD + 255) / 256, 256>>>((float*)d_out);
    k_pool<<<(NN * HD + 255) / 256, 256>>>(hin, batch, (float*)d_out);
}

// round 6
// speedup vs baseline: 2.1126x; 1.1937x over previous
#include <cuda_runtime.h>
#include <cuda_fp16.h>
#include <cstdint>

#define NN   20000
#define EE   320000
#define IND  128
#define HD   64
#define NH   4
#define QKVD 256   // NH * HD
#define NL   3
#define NG   128
#define NB   79    // scan blocks: ceil(NN/256)

// ---------------- scratch (device globals) ----------------------------------
__device__ float  g_h0[NN * HD];
__device__ float  g_h1[NN * HD];
__device__ float  g_q[NN * QKVD];
__device__ __half g_kh[NN * QKVD];
__device__ __half g_vh[NN * QKVD];
__device__ float  g_s[NN * HD];
__device__ int    g_cnt[NN];
__device__ int    g_rowptr[NN + 1];
__device__ int    g_cursor[NN];
__device__ int    g_srcs[EE];
__device__ int    g_bsum[128];
__device__ int    g_boff[128];
__device__ int    g_use32;   // 1 => edge_index/batch are int32, 0 => int64

__device__ __forceinline__ float* buf_sel(int s) {
    return s == 0 ? g_h0 : g_h1;
}

__device__ __forceinline__ int clampN(int i) {
    return i < 0 ? 0 : (i >= NN ? NN - 1 : i);
}
__device__ __forceinline__ int idx_at(const void* p, int i) {
    if (g_use32) return clampN(((const int*)p)[i]);
    return clampN((int)((const long long*)p)[i]);
}

// ---------------- dtype detection -------------------------------------------
__global__ void k_detect(const void* __restrict__ ei) {
    const long long* p = (const long long*)ei;
    int t = threadIdx.x;           // 32 threads
    long long v = p[t];
    unsigned bad = __ballot_sync(0xffffffffu, v < 0 || v >= (long long)NN);
    if (t == 0) g_use32 = (bad != 0u) ? 1 : 0;
}

// ---------------- CSR build (counting sort by dst) --------------------------
__global__ void k_zero_cnt() {
    int i = blockIdx.x * blockDim.x + threadIdx.x;
    if (i < NN) g_cnt[i] = 0;
}

__global__ void k_count(const void* __restrict__ ei) {
    int e = blockIdx.x * blockDim.x + threadIdx.x;
    if (e < EE) atomicAdd(&g_cnt[idx_at(ei, EE + e)], 1);
}

__global__ void k_scan1() {
    __shared__ int ws[8];
    int t = threadIdx.x, lane = t & 31, wid = t >> 5;
    int i = blockIdx.x * 256 + t;
    int v = (i < NN) ? g_cnt[i] : 0;
    int s = v;
    #pragma unroll
    for (int d = 16; d > 0; d >>= 1) s += __shfl_xor_sync(0xffffffffu, s, d);
    if (lane == 0) ws[wid] = s;
    __syncthreads();
    if (t < 8) {
        int x = ws[t];
        #pragma unroll
        for (int d = 4; d > 0; d >>= 1) x += __shfl_xor_sync(0xffu, x, d);
        if (t == 0) g_bsum[blockIdx.x] = x;
    }
}

__global__ void k_scan2() {
    __shared__ int wsum[4];
    int t = threadIdx.x, lane = t & 31, wid = t >> 5;
    int v = (t < NB) ? g_bsum[t] : 0;
    int incl = v;
    #pragma unroll
    for (int d = 1; d < 32; d <<= 1) {
        int nb = __shfl_up_sync(0xffffffffu, incl, d);
        if (lane >= d) incl += nb;
    }
    if (lane == 31) wsum[wid] = incl;
    __syncthreads();
    int off = 0;
    for (int w = 0; w < wid; w++) off += wsum[w];
    if (t < NB) g_boff[t] = off + incl - v;   // exclusive
}

__global__ void k_scan3() {
    __shared__ int wincl[8];
    int t = threadIdx.x, lane = t & 31, wid = t >> 5;
    int i = blockIdx.x * 256 + t;
    int v = (i < NN) ? g_cnt[i] : 0;
    int incl = v;
    #pragma unroll
    for (int d = 1; d < 32; d <<= 1) {
        int nb = __shfl_up_sync(0xffffffffu, incl, d);
        if (lane >= d) incl += nb;
    }
    if (lane == 31) wincl[wid] = incl;
    __syncthreads();
    int woff = 0;
    for (int w = 0; w < wid; w++) woff += wincl[w];
    int excl = g_boff[blockIdx.x] + woff + incl - v;
    if (i < NN) {
        g_cursor[i] = excl;
        g_rowptr[i + 1] = excl + v;
        if (i == 0) g_rowptr[0] = 0;
    }
}

__global__ void k_scatter(const void* __restrict__ ei) {
    int e = blockIdx.x * blockDim.x + threadIdx.x;
    if (e < EE) {
        int d   = idx_at(ei, EE + e);
        int pos = atomicAdd(&g_cursor[d], 1);
        g_srcs[pos] = idx_at(ei, e);
    }
}

// ---------------- TF32 tensor-core GEMM -------------------------------------
__device__ __forceinline__ uint32_t f2tf32(float f) {
    uint32_t u;
    asm("cvt.rna.tf32.f32 %0, %1;" : "=r"(u) : "f"(f));
    return u;
}

__device__ __forceinline__ void mma_tf32(float& c0, float& c1, float& c2, float& c3,
                                         uint32_t a0, uint32_t a1, uint32_t a2, uint32_t a3,
                                         uint32_t b0, uint32_t b1) {
    asm volatile(
        "mma.sync.aligned.m16n8k8.row.col.f32.tf32.tf32.f32 "
        "{%0,%1,%2,%3},{%4,%5,%6,%7},{%8,%9},{%0,%1,%2,%3};"
        : "+f"(c0), "+f"(c1), "+f"(c2), "+f"(c3)
        : "r"(a0), "r"(a1), "r"(a2), "r"(a3), "r"(b0), "r"(b1));
}

// C[64x64] tile via 8 warps (4m x 2n), warp tile m16n32.
// Output: fp32 to C if Ch==nullptr, else fp16 to Ch.
__device__ __forceinline__ void gemm_tile_tf32(
    const float* __restrict__ A, const float* __restrict__ W,
    const float* __restrict__ bias, float* __restrict__ C, __half* __restrict__ Ch,
    int n, int K, int Mw, int Mc, int row0, int colW, int colC) {

    __shared__ float As[64][68];
    __shared__ float Bs[64][68];

    int tid  = threadIdx.x;
    int lane = tid & 31;
    int wid  = tid >> 5;
    int wm   = wid & 3;
    int wn   = wid >> 2;
    int g    = lane >> 2;
    int tg   = lane & 3;

    float acc[4][4] = {};

    for (int kt = 0; kt < K; kt += 64) {
        #pragma unroll
        for (int i = 0; i < 4; i++) {
            int idx = i * 256 + tid;
            int r = idx >> 4, c4 = idx & 15;
            float4 av = make_float4(0.f, 0.f, 0.f, 0.f);
            int gr = row0 + r;
            if (gr < n) av = *(const float4*)(A + (size_t)gr * K + kt + c4 * 4);
            *(float4*)&As[r][c4 * 4] = av;
        }
        #pragma unroll
        for (int i = 0; i < 4; i++) {
            int idx = i * 256 + tid;
            int r = idx >> 4, c4 = idx & 15;
            float4 bv = *(const float4*)(W + (size_t)(kt + r) * Mw + colW + c4 * 4);
            *(float4*)&Bs[r][c4 * 4] = bv;
        }
        __syncthreads();

        #pragma unroll
        for (int ks = 0; ks < 8; ks++) {
            int k0 = ks * 8;
            uint32_t a0 = f2tf32(As[wm * 16 + g][k0 + tg]);
            uint32_t a1 = f2tf32(As[wm * 16 + g + 8][k0 + tg]);
            uint32_t a2 = f2tf32(As[wm * 16 + g][k0 + tg + 4]);
            uint32_t a3 = f2tf32(As[wm * 16 + g + 8][k0 + tg + 4]);
            #pragma unroll
            for (int j = 0; j < 4; j++) {
                int n0 = wn * 32 + j * 8;
                uint32_t b0 = f2tf32(Bs[k0 + tg][n0 + g]);
                uint32_t b1 = f2tf32(Bs[k0 + tg + 4][n0 + g]);
                mma_tf32(acc[j][0], acc[j][1], acc[j][2], acc[j][3],
                         a0, a1, a2, a3, b0, b1);
            }
        }
        __syncthreads();
    }

    #pragma unroll
    for (int j = 0; j < 4; j++) {
        int n0 = wn * 32 + j * 8;
        int cw = colW + n0 + tg * 2;
        int cc = colC + n0 + tg * 2;
        float b0 = bias[cw], b1 = bias[cw + 1];
        int r0 = row0 + wm * 16 + g;
        int r1 = r0 + 8;
        if (Ch) {
            if (r0 < n)
                *(__half2*)(Ch + (size_t)r0 * Mc + cc) =
                    __floats2half2_rn(acc[j][0] + b0, acc[j][1] + b1);
            if (r1 < n)
                *(__half2*)(Ch + (size_t)r1 * Mc + cc) =
                    __floats2half2_rn(acc[j][2] + b0, acc[j][3] + b1);
        } else {
            if (r0 < n)
                *(float2*)(C + (size_t)r0 * Mc + cc) =
                    make_float2(acc[j][0] + b0, acc[j][1] + b1);
            if (r1 < n)
                *(float2*)(C + (size_t)r1 * Mc + cc) =
                    make_float2(acc[j][2] + b0, acc[j][3] + b1);
        }
    }
}

// input projection: h0 = x @ lin_W + lin_b
__global__ __launch_bounds__(256) void k_gemm_in(const float* __restrict__ x,
                                                 const float* __restrict__ W,
                                                 const float* __restrict__ bias) {
    gemm_tile_tf32(x, W, bias, g_h0, nullptr, NN, IND, HD, HD, blockIdx.x * 64, 0, 0);
}

// fused q/k/v/s projections: grid.y = 13 col tiles (0-3 q, 4-7 k, 8-11 v, 12 s)
__global__ __launch_bounds__(256) void k_gemm_qkvs(int a_sel,
        const float* __restrict__ Wq, const float* __restrict__ bq,
        const float* __restrict__ Wk, const float* __restrict__ bk,
        const float* __restrict__ Wv, const float* __restrict__ bv,
        const float* __restrict__ Ws, const float* __restrict__ bs) {
    const float* A = buf_sel(a_sel);
    int ct = blockIdx.y;
    const float* W; const float* bias; float* C; __half* Ch; int M; int col;
    if (ct < 4)       { W = Wq; bias = bq; C = g_q; Ch = nullptr; M = QKVD; col = ct * 64; }
    else if (ct < 8)  { W = Wk; bias = bk; C = nullptr; Ch = g_kh; M = QKVD; col = (ct - 4) * 64; }
    else if (ct < 12) { W = Wv; bias = bv; C = nullptr; Ch = g_vh; M = QKVD; col = (ct - 8) * 64; }
    else              { W = Ws; bias = bs; C = g_s; Ch = nullptr; M = HD;   col = 0; }
    gemm_tile_tf32(A, W, bias, C, Ch, NN, HD, M, M, blockIdx.x * 64, col, col);
}

// ---------------- per-node attention: single-pass online softmax ------------
// one warp per node; lane = head*8 + t; lane owns 8 contiguous columns.
// k/v are fp16: 8 halves = one uint4 per lane per row. Software-pipelined.
__global__ void k_attn(int out_sel) {
    int node = (blockIdx.x * blockDim.x + threadIdx.x) >> 5;
    if (node >= NN) return;
    float* hout = buf_sel(out_sel);
    int lane = threadIdx.x & 31;
    int h = lane >> 3, t = lane & 7;
    int col = h * 64 + t * 8;

    const float4* qp = (const float4*)(g_q + (size_t)node * QKVD + col);
    float4 qa = qp[0], qb = qp[1];

    int beg = g_rowptr[node], end = g_rowptr[node + 1];

    float m = -1e30f, denom = 0.f;
    float acc[8] = {0.f, 0.f, 0.f, 0.f, 0.f, 0.f, 0.f, 0.f};

    uint4 kw, vw;
    if (beg < end) {
        int s0 = g_srcs[beg];
        kw = *(const uint4*)(g_kh + (size_t)s0 * QKVD + col);
        vw = *(const uint4*)(g_vh + (size_t)s0 * QKVD + col);
    }

    for (int p = beg; p < end; ++p) {
        uint4 kc = kw, vc = vw;
        if (p + 1 < end) {
            int s1 = g_srcs[p + 1];
            kw = *(const uint4*)(g_kh + (size_t)s1 * QKVD + col);
            vw = *(const uint4*)(g_vh + (size_t)s1 * QKVD + col);
        }

        const __half2* kh = (const __half2*)&kc;
        float2 k0 = __half22float2(kh[0]);
        float2 k1 = __half22float2(kh[1]);
        float2 k2 = __half22float2(kh[2]);
        float2 k3 = __half22float2(kh[3]);

        float d = qa.x * k0.x + qa.y * k0.y + qa.z * k1.x + qa.w * k1.y
                + qb.x * k2.x + qb.y * k2.y + qb.z * k3.x + qb.w * k3.y;
        d += __shfl_xor_sync(0xffffffffu, d, 1);
        d += __shfl_xor_sync(0xffffffffu, d, 2);
        d += __shfl_xor_sync(0xffffffffu, d, 4);
        d *= 0.125f;                       // 1/sqrt(64)

        float nm   = fmaxf(m, d);
        float corr = __expf(m - nm);
        float ex   = __expf(d - nm);
        m = nm;
        denom = denom * corr + ex;

        const __half2* vh = (const __half2*)&vc;
        float2 v0 = __half22float2(vh[0]);
        float2 v1 = __half22float2(vh[1]);
        float2 v2 = __half22float2(vh[2]);
        float2 v3 = __half22float2(vh[3]);
        acc[0] = acc[0] * corr + ex * v0.x;
        acc[1] = acc[1] * corr + ex * v0.y;
        acc[2] = acc[2] * corr + ex * v1.x;
        acc[3] = acc[3] * corr + ex * v1.y;
        acc[4] = acc[4] * corr + ex * v2.x;
        acc[5] = acc[5] * corr + ex * v2.y;
        acc[6] = acc[6] * corr + ex * v3.x;
        acc[7] = acc[7] * corr + ex * v3.y;
    }
    float inv = denom > 0.f ? 1.f / denom : 0.f;

    #pragma unroll
    for (int j = 0; j < 8; j++) {
        float o = acc[j] * inv;
        o += __shfl_xor_sync(0xffffffffu, o, 8);
        o += __shfl_xor_sync(0xffffffffu, o, 16);
        acc[j] = o;
    }

    if (h == 0) {
        const float* sp = g_s + (size_t)node * HD + t * 8;
        float* op = hout + (size_t)node * HD + t * 8;
        #pragma unroll
        for (int j = 0; j < 8; j++) {
            float val = 0.25f * acc[j] + sp[j];   // head mean + skip
            op[j] = fmaxf(val, 0.f);              // ReLU
        }
    }
}

// ---------------- global add pool -------------------------------------------
__global__ void k_pool_zero(float* out) {
    int i = blockIdx.x * blockDim.x + threadIdx.x;
    if (i < NG * HD) out[i] = 0.f;
}

__global__ void k_pool(int in_sel, const void* __restrict__ batch,
                       float* out) {
    const float* hh = buf_sel(in_sel);
    int i = blockIdx.x * blockDim.x + threadIdx.x;
    if (i < NN * HD) {
        int row = i >> 6;
        int g = g_use32 ? ((const int*)batch)[row]
                        : (int)((const long long*)batch)[row];
        g = g < 0 ? 0 : (g >= NG ? NG - 1 : g);
        atomicAdd(&out[g * HD + (i & 63)], hh[i]);
    }
}

// ---------------- host ------------------------------------------------------
extern "C" void kernel_launch(void* const* d_in, const int* in_sizes, int n_in,
                              void* d_out, int out_size) {
    (void)in_sizes; (void)n_in; (void)out_size;
    const float* x     = (const float*)d_in[0];
    const void*  ei    = d_in[1];
    const void*  batch = d_in[2];
    const float* lin_W = (const float*)d_in[3];
    const float* lin_b = (const float*)d_in[4];
    const float* Wq = (const float*)d_in[5];
    const float* bq = (const float*)d_in[6];
    const float* Wk = (const float*)d_in[7];
    const float* bk = (const float*)d_in[8];
    const float* Wv = (const float*)d_in[9];
    const float* bv = (const float*)d_in[10];
    const float* Ws = (const float*)d_in[11];
    const float* bs = (const float*)d_in[12];

    // dtype detect + CSR by dst
    k_detect<<<1, 32>>>(ei);
    k_zero_cnt<<<(NN + 255) / 256, 256>>>();
    k_count<<<(EE + 255) / 256, 256>>>(ei);
    k_scan1<<<NB, 256>>>();
    k_scan2<<<1, 128>>>();
    k_scan3<<<NB, 256>>>();
    k_scatter<<<(EE + 255) / 256, 256>>>(ei);

    const int RT = (NN + 63) / 64;  // 313 row tiles

    k_gemm_in<<<dim3(RT, 1), 256>>>(x, lin_W, lin_b);

    int hin = 0, hou = 1;
    for (int l = 0; l < NL; l++) {
        k_gemm_qkvs<<<dim3(RT, 13), 256>>>(hin,
            Wq + (size_t)l * HD * QKVD, bq + (size_t)l * QKVD,
            Wk + (size_t)l * HD * QKVD, bk + (size_t)l * QKVD,
            Wv + (size_t)l * HD * QKVD, bv + (size_t)l * QKVD,
            Ws + (size_t)l * HD * HD,   bs + (size_t)l * HD);
        k_attn<<<(NN * 32 + 255) / 256, 256>>>(hou);
        int tmp = hin; hin = hou; hou = tmp;
    }

    k_pool_zero<<<(NG * HD + 255) / 256, 256>>>((float*)d_out);
    k_pool<<<(NN * HD + 255) / 256, 256>>>(hin, batch, (float*)d_out);
}

// round 7
// speedup vs baseline: 2.1653x; 1.0250x over previous
#include <cuda_runtime.h>
#include <cuda_fp16.h>
#include <cstdint>

#define NN   20000
#define EE   320000
#define IND  128
#define HD   64
#define NH   4
#define QKVD 256   // NH * HD
#define NL   3
#define NG   128
#define NB   79    // scan blocks: ceil(NN/256)

// ---------------- scratch (device globals) ----------------------------------
__device__ float  g_h0[NN * HD];
__device__ float  g_h1[NN * HD];
__device__ float  g_q[NN * QKVD];
__device__ __half g_kh[NN * QKVD];
__device__ __half g_vh[NN * QKVD];
__device__ float  g_s[NN * HD];
__device__ int    g_cnt[NN];
__device__ int    g_rowptr[NN + 1];
__device__ int    g_cursor[NN];
__device__ int    g_srcs[EE];
__device__ int    g_bsum[128];
__device__ int    g_boff[128];
__device__ int    g_use32;   // 1 => edge_index/batch are int32, 0 => int64

__device__ __forceinline__ float* buf_sel(int s) {
    return s == 0 ? g_h0 : g_h1;
}

__device__ __forceinline__ int clampN(int i) {
    return i < 0 ? 0 : (i >= NN ? NN - 1 : i);
}
__device__ __forceinline__ int idx_at(const void* p, int i) {
    if (g_use32) return clampN(((const int*)p)[i]);
    return clampN((int)((const long long*)p)[i]);
}

// ---------------- dtype detection -------------------------------------------
__global__ void k_detect(const void* __restrict__ ei) {
    const long long* p = (const long long*)ei;
    int t = threadIdx.x;           // 32 threads
    long long v = p[t];
    unsigned bad = __ballot_sync(0xffffffffu, v < 0 || v >= (long long)NN);
    if (t == 0) g_use32 = (bad != 0u) ? 1 : 0;
}

// ---------------- CSR build (counting sort by dst) --------------------------
__global__ void k_zero_cnt() {
    int i = blockIdx.x * blockDim.x + threadIdx.x;
    if (i < NN) g_cnt[i] = 0;
}

__global__ void k_count(const void* __restrict__ ei) {
    int e = blockIdx.x * blockDim.x + threadIdx.x;
    if (e < EE) atomicAdd(&g_cnt[idx_at(ei, EE + e)], 1);
}

__global__ void k_scan1() {
    __shared__ int ws[8];
    int t = threadIdx.x, lane = t & 31, wid = t >> 5;
    int i = blockIdx.x * 256 + t;
    int v = (i < NN) ? g_cnt[i] : 0;
    int s = v;
    #pragma unroll
    for (int d = 16; d > 0; d >>= 1) s += __shfl_xor_sync(0xffffffffu, s, d);
    if (lane == 0) ws[wid] = s;
    __syncthreads();
    if (t < 8) {
        int x = ws[t];
        #pragma unroll
        for (int d = 4; d > 0; d >>= 1) x += __shfl_xor_sync(0xffu, x, d);
        if (t == 0) g_bsum[blockIdx.x] = x;
    }
}

__global__ void k_scan2() {
    __shared__ int wsum[4];
    int t = threadIdx.x, lane = t & 31, wid = t >> 5;
    int v = (t < NB) ? g_bsum[t] : 0;
    int incl = v;
    #pragma unroll
    for (int d = 1; d < 32; d <<= 1) {
        int nb = __shfl_up_sync(0xffffffffu, incl, d);
        if (lane >= d) incl += nb;
    }
    if (lane == 31) wsum[wid] = incl;
    __syncthreads();
    int off = 0;
    for (int w = 0; w < wid; w++) off += wsum[w];
    if (t < NB) g_boff[t] = off + incl - v;   // exclusive
}

__global__ void k_scan3() {
    __shared__ int wincl[8];
    int t = threadIdx.x, lane = t & 31, wid = t >> 5;
    int i = blockIdx.x * 256 + t;
    int v = (i < NN) ? g_cnt[i] : 0;
    int incl = v;
    #pragma unroll
    for (int d = 1; d < 32; d <<= 1) {
        int nb = __shfl_up_sync(0xffffffffu, incl, d);
        if (lane >= d) incl += nb;
    }
    if (lane == 31) wincl[wid] = incl;
    __syncthreads();
    int woff = 0;
    for (int w = 0; w < wid; w++) woff += wincl[w];
    int excl = g_boff[blockIdx.x] + woff + incl - v;
    if (i < NN) {
        g_cursor[i] = excl;
        g_rowptr[i + 1] = excl + v;
        if (i == 0) g_rowptr[0] = 0;
    }
}

__global__ void k_scatter(const void* __restrict__ ei) {
    int e = blockIdx.x * blockDim.x + threadIdx.x;
    if (e < EE) {
        int d   = idx_at(ei, EE + e);
        int pos = atomicAdd(&g_cursor[d], 1);
        g_srcs[pos] = idx_at(ei, e);
    }
}

// ---------------- TF32 tensor-core GEMM -------------------------------------
__device__ __forceinline__ uint32_t f2tf32(float f) {
    uint32_t u;
    asm("cvt.rna.tf32.f32 %0, %1;" : "=r"(u) : "f"(f));
    return u;
}

__device__ __forceinline__ void mma_tf32(float& c0, float& c1, float& c2, float& c3,
                                         uint32_t a0, uint32_t a1, uint32_t a2, uint32_t a3,
                                         uint32_t b0, uint32_t b1) {
    asm volatile(
        "mma.sync.aligned.m16n8k8.row.col.f32.tf32.tf32.f32 "
        "{%0,%1,%2,%3},{%4,%5,%6,%7},{%8,%9},{%0,%1,%2,%3};"
        : "+f"(c0), "+f"(c1), "+f"(c2), "+f"(c3)
        : "r"(a0), "r"(a1), "r"(a2), "r"(a3), "r"(b0), "r"(b1));
}

// C[64x64] tile via 8 warps (4m x 2n), warp tile m16n32.
// tf32 conversion hoisted to the smem store; inner loop is pure LDS + HMMA.
// Output: fp32 to C if Ch==nullptr, else fp16 to Ch.
__device__ __forceinline__ void gemm_tile_tf32(
    const float* __restrict__ A, const float* __restrict__ W,
    const float* __restrict__ bias, float* __restrict__ C, __half* __restrict__ Ch,
    int n, int K, int Mw, int Mc, int row0, int colW, int colC) {

    __shared__ uint32_t As[64][68];
    __shared__ uint32_t Bs[64][68];

    int tid  = threadIdx.x;
    int lane = tid & 31;
    int wid  = tid >> 5;
    int wm   = wid & 3;
    int wn   = wid >> 2;
    int g    = lane >> 2;
    int tg   = lane & 3;

    float acc[4][4] = {};

    for (int kt = 0; kt < K; kt += 64) {
        #pragma unroll
        for (int i = 0; i < 4; i++) {
            int idx = i * 256 + tid;
            int r = idx >> 4, c4 = idx & 15;
            float4 av = make_float4(0.f, 0.f, 0.f, 0.f);
            int gr = row0 + r;
            if (gr < n) av = *(const float4*)(A + (size_t)gr * K + kt + c4 * 4);
            uint4 at;
            at.x = f2tf32(av.x); at.y = f2tf32(av.y);
            at.z = f2tf32(av.z); at.w = f2tf32(av.w);
            *(uint4*)&As[r][c4 * 4] = at;
        }
        #pragma unroll
        for (int i = 0; i < 4; i++) {
            int idx = i * 256 + tid;
            int r = idx >> 4, c4 = idx & 15;
            float4 bv = *(const float4*)(W + (size_t)(kt + r) * Mw + colW + c4 * 4);
            uint4 bt;
            bt.x = f2tf32(bv.x); bt.y = f2tf32(bv.y);
            bt.z = f2tf32(bv.z); bt.w = f2tf32(bv.w);
            *(uint4*)&Bs[r][c4 * 4] = bt;
        }
        __syncthreads();

        #pragma unroll
        for (int ks = 0; ks < 8; ks++) {
            int k0 = ks * 8;
            uint32_t a0 = As[wm * 16 + g][k0 + tg];
            uint32_t a1 = As[wm * 16 + g + 8][k0 + tg];
            uint32_t a2 = As[wm * 16 + g][k0 + tg + 4];
            uint32_t a3 = As[wm * 16 + g + 8][k0 + tg + 4];
            #pragma unroll
            for (int j = 0; j < 4; j++) {
                int n0 = wn * 32 + j * 8;
                uint32_t b0 = Bs[k0 + tg][n0 + g];
                uint32_t b1 = Bs[k0 + tg + 4][n0 + g];
                mma_tf32(acc[j][0], acc[j][1], acc[j][2], acc[j][3],
                         a0, a1, a2, a3, b0, b1);
            }
        }
        __syncthreads();
    }

    #pragma unroll
    for (int j = 0; j < 4; j++) {
        int n0 = wn * 32 + j * 8;
        int cw = colW + n0 + tg * 2;
        int cc = colC + n0 + tg * 2;
        float b0 = bias[cw], b1 = bias[cw + 1];
        int r0 = row0 + wm * 16 + g;
        int r1 = r0 + 8;
        if (Ch) {
            if (r0 < n)
                *(__half2*)(Ch + (size_t)r0 * Mc + cc) =
                    __floats2half2_rn(acc[j][0] + b0, acc[j][1] + b1);
            if (r1 < n)
                *(__half2*)(Ch + (size_t)r1 * Mc + cc) =
                    __floats2half2_rn(acc[j][2] + b0, acc[j][3] + b1);
        } else {
            if (r0 < n)
                *(float2*)(C + (size_t)r0 * Mc + cc) =
                    make_float2(acc[j][0] + b0, acc[j][1] + b1);
            if (r1 < n)
                *(float2*)(C + (size_t)r1 * Mc + cc) =
                    make_float2(acc[j][2] + b0, acc[j][3] + b1);
        }
    }
}

// input projection: h0 = x @ lin_W + lin_b
__global__ __launch_bounds__(256) void k_gemm_in(const float* __restrict__ x,
                                                 const float* __restrict__ W,
                                                 const float* __restrict__ bias) {
    gemm_tile_tf32(x, W, bias, g_h0, nullptr, NN, IND, HD, HD, blockIdx.x * 64, 0, 0);
}

// fused q/k/v/s projections: grid.y = 13 col tiles (0-3 q, 4-7 k, 8-11 v, 12 s)
__global__ __launch_bounds__(256) void k_gemm_qkvs(int a_sel,
        const float* __restrict__ Wq, const float* __restrict__ bq,
        const float* __restrict__ Wk, const float* __restrict__ bk,
        const float* __restrict__ Wv, const float* __restrict__ bv,
        const float* __restrict__ Ws, const float* __restrict__ bs) {
    const float* A = buf_sel(a_sel);
    int ct = blockIdx.y;
    const float* W; const float* bias; float* C; __half* Ch; int M; int col;
    if (ct < 4)       { W = Wq; bias = bq; C = g_q; Ch = nullptr; M = QKVD; col = ct * 64; }
    else if (ct < 8)  { W = Wk; bias = bk; C = nullptr; Ch = g_kh; M = QKVD; col = (ct - 4) * 64; }
    else if (ct < 12) { W = Wv; bias = bv; C = nullptr; Ch = g_vh; M = QKVD; col = (ct - 8) * 64; }
    else              { W = Ws; bias = bs; C = g_s; Ch = nullptr; M = HD;   col = 0; }
    gemm_tile_tf32(A, W, bias, C, Ch, NN, HD, M, M, blockIdx.x * 64, col, col);
}

// ---------------- per-node attention: single-pass online softmax ------------
__global__ void k_attn(int out_sel) {
    int node = (blockIdx.x * blockDim.x + threadIdx.x) >> 5;
    if (node >= NN) return;
    float* hout = buf_sel(out_sel);
    int lane = threadIdx.x & 31;
    int h = lane >> 3, t = lane & 7;
    int col = h * 64 + t * 8;

    const float4* qp = (const float4*)(g_q + (size_t)node * QKVD + col);
    float4 qa = qp[0], qb = qp[1];

    int beg = g_rowptr[node], end = g_rowptr[node + 1];

    float m = -1e30f, denom = 0.f;
    float acc[8] = {0.f, 0.f, 0.f, 0.f, 0.f, 0.f, 0.f, 0.f};

    uint4 kw, vw;
    if (beg < end) {
        int s0 = g_srcs[beg];
        kw = *(const uint4*)(g_kh + (size_t)s0 * QKVD + col);
        vw = *(const uint4*)(g_vh + (size_t)s0 * QKVD + col);
    }

    for (int p = beg; p < end; ++p) {
        uint4 kc = kw, vc = vw;
        if (p + 1 < end) {
            int s1 = g_srcs[p + 1];
            kw = *(const uint4*)(g_kh + (size_t)s1 * QKVD + col);
            vw = *(const uint4*)(g_vh + (size_t)s1 * QKVD + col);
        }

        const __half2* kh = (const __half2*)&kc;
        float2 k0 = __half22float2(kh[0]);
        float2 k1 = __half22float2(kh[1]);
        float2 k2 = __half22float2(kh[2]);
        float2 k3 = __half22float2(kh[3]);

        float d = qa.x * k0.x + qa.y * k0.y + qa.z * k1.x + qa.w * k1.y
                + qb.x * k2.x + qb.y * k2.y + qb.z * k3.x + qb.w * k3.y;
        d += __shfl_xor_sync(0xffffffffu, d, 1);
        d += __shfl_xor_sync(0xffffffffu, d, 2);
        d += __shfl_xor_sync(0xffffffffu, d, 4);
        d *= 0.125f;                       // 1/sqrt(64)

        float nm   = fmaxf(m, d);
        float corr = __expf(m - nm);
        float ex   = __expf(d - nm);
        m = nm;
        denom = denom * corr + ex;

        const __half2* vh = (const __half2*)&vc;
        float2 v0 = __half22float2(vh[0]);
        float2 v1 = __half22float2(vh[1]);
        float2 v2 = __half22float2(vh[2]);
        float2 v3 = __half22float2(vh[3]);
        acc[0] = acc[0] * corr + ex * v0.x;
        acc[1] = acc[1] * corr + ex * v0.y;
        acc[2] = acc[2] * corr + ex * v1.x;
        acc[3] = acc[3] * corr + ex * v1.y;
        acc[4] = acc[4] * corr + ex * v2.x;
        acc[5] = acc[5] * corr + ex * v2.y;
        acc[6] = acc[6] * corr + ex * v3.x;
        acc[7] = acc[7] * corr + ex * v3.y;
    }
    float inv = denom > 0.f ? 1.f / denom : 0.f;

    #pragma unroll
    for (int j = 0; j < 8; j++) {
        float o = acc[j] * inv;
        o += __shfl_xor_sync(0xffffffffu, o, 8);
        o += __shfl_xor_sync(0xffffffffu, o, 16);
        acc[j] = o;
    }

    if (h == 0) {
        const float* sp = g_s + (size_t)node * HD + t * 8;
        float* op = hout + (size_t)node * HD + t * 8;
        #pragma unroll
        for (int j = 0; j < 8; j++) {
            float val = 0.25f * acc[j] + sp[j];   // head mean + skip
            op[j] = fmaxf(val, 0.f);              // ReLU
        }
    }
}

// ---------------- global add pool -------------------------------------------
__global__ void k_pool_zero(float* out) {
    int i = blockIdx.x * blockDim.x + threadIdx.x;
    if (i < NG * HD) out[i] = 0.f;
}

__global__ void k_pool(int in_sel, const void* __restrict__ batch,
                       float* out) {
    const float* hh = buf_sel(in_sel);
    int i = blockIdx.x * blockDim.x + threadIdx.x;
    if (i < NN * HD) {
        int row = i >> 6;
        int g = g_use32 ? ((const int*)batch)[row]
                        : (int)((const long long*)batch)[row];
        g = g < 0 ? 0 : (g >= NG ? NG - 1 : g);
        atomicAdd(&out[g * HD + (i & 63)], hh[i]);
    }
}

// ---------------- host ------------------------------------------------------
extern "C" void kernel_launch(void* const* d_in, const int* in_sizes, int n_in,
                              void* d_out, int out_size) {
    (void)in_sizes; (void)n_in; (void)out_size;
    const float* x     = (const float*)d_in[0];
    const void*  ei    = d_in[1];
    const void*  batch = d_in[2];
    const float* lin_W = (const float*)d_in[3];
    const float* lin_b = (const float*)d_in[4];
    const float* Wq = (const float*)d_in[5];
    const float* bq = (const float*)d_in[6];
    const float* Wk = (const float*)d_in[7];
    const float* bk = (const float*)d_in[8];
    const float* Wv = (const float*)d_in[9];
    const float* bv = (const float*)d_in[10];
    const float* Ws = (const float*)d_in[11];
    const float* bs = (const float*)d_in[12];

    // side stream for the CSR build (fork/join is capture-legal)
    cudaStream_t s2;
    cudaStreamCreateWithFlags(&s2, cudaStreamNonBlocking);
    cudaEvent_t eFork, eJoin;
    cudaEventCreateWithFlags(&eFork, cudaEventDisableTiming);
    cudaEventCreateWithFlags(&eJoin, cudaEventDisableTiming);

    cudaEventRecord(eFork, 0);
    cudaStreamWaitEvent(s2, eFork, 0);

    // CSR by dst — on s2, overlapping the GEMM chain
    k_detect<<<1, 32, 0, s2>>>(ei);
    k_zero_cnt<<<(NN + 255) / 256, 256, 0, s2>>>();
    k_count<<<(EE + 255) / 256, 256, 0, s2>>>(ei);
    k_scan1<<<NB, 256, 0, s2>>>();
    k_scan2<<<1, 128, 0, s2>>>();
    k_scan3<<<NB, 256, 0, s2>>>();
    k_scatter<<<(EE + 255) / 256, 256, 0, s2>>>(ei);
    cudaEventRecord(eJoin, s2);

    const int RT = (NN + 63) / 64;  // 313 row tiles

    k_gemm_in<<<dim3(RT, 1), 256>>>(x, lin_W, lin_b);

    int hin = 0, hou = 1;
    for (int l = 0; l < NL; l++) {
        k_gemm_qkvs<<<dim3(RT, 13), 256>>>(hin,
            Wq + (size_t)l * HD * QKVD, bq + (size_t)l * QKVD,
            Wk + (size_t)l * HD * QKVD, bk + (size_t)l * QKVD,
            Wv + (size_t)l * HD * QKVD, bv + (size_t)l * QKVD,
            Ws + (size_t)l * HD * HD,   bs + (size_t)l * HD);
        if (l == 0) cudaStreamWaitEvent(0, eJoin, 0);   // CSR ready before attn
        k_attn<<<(NN * 32 + 255) / 256, 256>>>(hou);
        int tmp = hin; hin = hou; hou = tmp;
    }

    k_pool_zero<<<(NG * HD + 255) / 256, 256>>>((float*)d_out);
    k_pool<<<(NN * HD + 255) / 256, 256>>>(hin, batch, (float*)d_out);
}